// round 6
// baseline (speedup 1.0000x reference)
#include <cuda_runtime.h>
#include <math.h>
#include <stdint.h>

// Problem constants
#define MTOK   32768
#define DDIM   2048
#define NEXP   64
#define TOPK   8
#define NCOLS  128           // router(64) || noise(64)

// Tiling
#define BM      64           // tokens per CTA
#define DK      32           // k-chunk
#define NTHREADS 256         // tx: 16 col-groups (8 cols), ty: 16 token-groups (4 tokens)
#define NKB     (DDIM / DK)  // 64 chunks

// smem: two buffers, each [xs | ws]; epilogue ls aliases the front.
#define XROW      132                       // floats per xs row (dup pairs, 16B-aligned, 2-way-max store conflicts)
#define XS_BYTES  (DK * XROW * 4)           // 16896
#define WS_BYTES  (DK * NCOLS * 4)          // 16384
#define BUF_BYTES (XS_BYTES + WS_BYTES)     // 33280
#define SMEM_BYTES (2 * BUF_BYTES)          // 66560
#define LSTRIDE   133                       // 64*133*4 = 34048 <= SMEM_BYTES

typedef unsigned long long ull;

__device__ __forceinline__ void fma2(ull &acc, ull a, ull b) {
    asm("fma.rn.f32x2 %0, %1, %2, %0;" : "+l"(acc) : "l"(a), "l"(b));
}
__device__ __forceinline__ void add2(ull &acc, ull a) {
    asm("add.rn.f32x2 %0, %0, %1;" : "+l"(acc) : "l"(a));
}
__device__ __forceinline__ float lo2(ull v) { return __uint_as_float((unsigned)v); }
__device__ __forceinline__ float hi2(ull v) { return __uint_as_float((unsigned)(v >> 32)); }

__device__ __forceinline__ void cp16(uint32_t dst_smem, const void* src) {
    asm volatile("cp.async.ca.shared.global [%0], [%1], 16;\n" :: "r"(dst_smem), "l"(src));
}
__device__ __forceinline__ void cp_commit() { asm volatile("cp.async.commit_group;\n"); }
__device__ __forceinline__ void cp_wait()   { asm volatile("cp.async.wait_group 0;\n" ::: "memory"); }

__global__ __launch_bounds__(NTHREADS, 2) void router_kernel(
    const float* __restrict__ x,     const float* __restrict__ eps,
    const float* __restrict__ wr,    const float* __restrict__ br,
    const float* __restrict__ wn,    const float* __restrict__ bn,
    const float* __restrict__ wskip, const float* __restrict__ bskip,
    float* __restrict__ out_router, float* __restrict__ out_idx,
    float* __restrict__ out_skip)
{
    extern __shared__ __align__(16) unsigned char smem[];
    float (*ls)[LSTRIDE] = (float(*)[LSTRIDE])smem;   // epilogue only (aliases buffers)

    uint32_t sbase;
    asm("{ .reg .u64 t; cvta.to.shared.u64 t, %1; cvt.u32.u64 %0, t; }"
        : "=r"(sbase) : "l"(smem));

    const int tid = threadIdx.x;
    const int tx  = tid & 15;     // col group: cols 4tx + {0..3}, 4tx+64 + {0..3}
    const int ty  = tid >> 4;     // tokens ty*4 .. ty*4+3
    const int dq  = tid & 7;      // x-prefetch d-quad
    const int tokA = tid >> 3;    // 0..31
    const int m0  = blockIdx.x * BM;

    // ---- accumulators ----
    ull acc[4][4];                // [tok][pair]: pair p -> cols 4tx + 64*(p>>1) + 2*(p&1) + {0,1}
    #pragma unroll
    for (int t = 0; t < 4; t++)
        #pragma unroll
        for (int p = 0; p < 4; p++) acc[t][p] = 0ull;
    float skA = 0.f, skB = 0.f;   // skip-dot partials for tokens tokA, tokA+32

    // ================= prologue: fill buffer 0 (chunk 0) =================
    float4 xA, xB;
    {
        xA = *(const float4*)(x + (size_t)(m0 + tokA) * DDIM + dq * 4);
        xB = *(const float4*)(x + (size_t)(m0 + tokA + 32) * DDIM + dq * 4);
        float4 w4 = *(const float4*)(wskip + dq * 4);
        skA = fmaf(xA.x, w4.x, fmaf(xA.y, w4.y, fmaf(xA.z, w4.z, xA.w * w4.w)));
        skB = fmaf(xB.x, w4.x, fmaf(xB.y, w4.y, fmaf(xB.z, w4.z, xB.w * w4.w)));
        // w panel via cp.async
        #pragma unroll
        for (int i = 0; i < 4; i++) {
            int fid = tid + i * NTHREADS;
            int d   = fid >> 5;
            int col = (fid & 31) * 4;
            const float* src = (col < 64) ? (wr + (size_t)d * NEXP + col)
                                          : (wn + (size_t)d * NEXP + (col - 64));
            cp16(sbase + XS_BYTES + (uint32_t)(d * NCOLS + col) * 4, src);
        }
        cp_commit();
        // x dup stores
        float* xs0 = (float*)smem;
        float va[4] = {xA.x, xA.y, xA.z, xA.w};
        float vb[4] = {xB.x, xB.y, xB.z, xB.w};
        #pragma unroll
        for (int j = 0; j < 4; j++) {
            *(float2*)&xs0[(4 * dq + j) * XROW + 2 * tokA]        = make_float2(va[j], va[j]);
            *(float2*)&xs0[(4 * dq + j) * XROW + 2 * (tokA + 32)] = make_float2(vb[j], vb[j]);
        }
        cp_wait();
    }
    __syncthreads();

    // ================= main loop =================
    for (int kb = 0; kb < NKB; kb++) {
        const int cur = kb & 1;
        const uint32_t curoff = (uint32_t)cur * BUF_BYTES;
        const float* xsb = (const float*)(smem + curoff);
        const float* wsb = (const float*)(smem + curoff + XS_BYTES);

        // ---- prefetch chunk kb+1 into the other buffer ----
        if (kb < NKB - 1) {
            const int k0 = (kb + 1) * DK;
            xA = *(const float4*)(x + (size_t)(m0 + tokA) * DDIM + k0 + dq * 4);
            xB = *(const float4*)(x + (size_t)(m0 + tokA + 32) * DDIM + k0 + dq * 4);
            float4 w4 = *(const float4*)(wskip + k0 + dq * 4);
            skA = fmaf(xA.x, w4.x, fmaf(xA.y, w4.y, fmaf(xA.z, w4.z, fmaf(xA.w, w4.w, skA))));
            skB = fmaf(xB.x, w4.x, fmaf(xB.y, w4.y, fmaf(xB.z, w4.z, fmaf(xB.w, w4.w, skB))));
            const uint32_t nxtoff = (uint32_t)(cur ^ 1) * BUF_BYTES;
            #pragma unroll
            for (int i = 0; i < 4; i++) {
                int fid = tid + i * NTHREADS;
                int d   = fid >> 5;
                int col = (fid & 31) * 4;
                const float* src = (col < 64) ? (wr + (size_t)(k0 + d) * NEXP + col)
                                              : (wn + (size_t)(k0 + d) * NEXP + (col - 64));
                cp16(sbase + nxtoff + XS_BYTES + (uint32_t)(d * NCOLS + col) * 4, src);
            }
            cp_commit();
        }

        // ---- FFMA2 mainloop over current buffer ----
        ull inner[4][4];
        #pragma unroll
        for (int t = 0; t < 4; t++)
            #pragma unroll
            for (int p = 0; p < 4; p++) inner[t][p] = 0ull;

        #pragma unroll
        for (int d = 0; d < DK; d++) {
            ulonglong2 xv0 = *(const ulonglong2*)(xsb + d * XROW + 8 * ty);      // tokens t0,t1 dup
            ulonglong2 xv1 = *(const ulonglong2*)(xsb + d * XROW + 8 * ty + 4);  // tokens t2,t3 dup
            ulonglong2 wA  = *(const ulonglong2*)(wsb + d * NCOLS + 4 * tx);
            ulonglong2 wB  = *(const ulonglong2*)(wsb + d * NCOLS + 4 * tx + 64);
            ull x2[4] = {xv0.x, xv0.y, xv1.x, xv1.y};
            #pragma unroll
            for (int t = 0; t < 4; t++) {
                fma2(inner[t][0], x2[t], wA.x);
                fma2(inner[t][1], x2[t], wA.y);
                fma2(inner[t][2], x2[t], wB.x);
                fma2(inner[t][3], x2[t], wB.y);
            }
        }
        #pragma unroll
        for (int t = 0; t < 4; t++)
            #pragma unroll
            for (int p = 0; p < 4; p++) add2(acc[t][p], inner[t][p]);

        // ---- store prefetched x into next buffer, drain cp.async ----
        if (kb < NKB - 1) {
            float* xsn = (float*)(smem + (size_t)(cur ^ 1) * BUF_BYTES);
            float va[4] = {xA.x, xA.y, xA.z, xA.w};
            float vb[4] = {xB.x, xB.y, xB.z, xB.w};
            #pragma unroll
            for (int j = 0; j < 4; j++) {
                *(float2*)&xsn[(4 * dq + j) * XROW + 2 * tokA]        = make_float2(va[j], va[j]);
                *(float2*)&xsn[(4 * dq + j) * XROW + 2 * (tokA + 32)] = make_float2(vb[j], vb[j]);
            }
            cp_wait();
        }
        __syncthreads();
    }

    // ---- stage logits (+bias) into ls (aliases buffers; all reads done) ----
    #pragma unroll
    for (int t = 0; t < 4; t++) {
        int tok = ty * 4 + t;
        #pragma unroll
        for (int p = 0; p < 4; p++) {
            int c0 = 4 * tx + 64 * (p >> 1) + 2 * (p & 1);
            float b0 = (c0 < 64) ? __ldg(br + c0) : __ldg(bn + c0 - 64);
            float b1 = (c0 + 1 < 64) ? __ldg(br + c0 + 1) : __ldg(bn + c0 + 1 - 64);
            ls[tok][c0]     = __fadd_rn(lo2(acc[t][p]), b0);
            ls[tok][c0 + 1] = __fadd_rn(hi2(acc[t][p]), b1);
        }
    }
    // ---- skip-dot reduction across the 8 dq lanes per token ----
    #pragma unroll
    for (int m = 1; m < 8; m <<= 1) {
        skA += __shfl_xor_sync(0xffffffffu, skA, m);
        skB += __shfl_xor_sync(0xffffffffu, skB, m);
    }
    if (dq == 0) {
        float b = __ldg(bskip);
        ls[tokA][128]      = __fadd_rn(skA, b);
        ls[tokA + 32][128] = __fadd_rn(skB, b);
    }
    __syncthreads();

    // ---- noisy logits: parallel over all 256 threads ----
    #pragma unroll
    for (int i = 0; i < 16; i++) {
        int fid = tid + i * NTHREADS;
        int tok = fid >> 6;
        int e   = fid & 63;
        float  lg = ls[tok][e];
        float  no = ls[tok][64 + e];
        double nd = (double)no;
        float  sp = (float)(fmax(nd, 0.0) + log1p(exp(-fabs(nd))));
        float  ev = __ldg(eps + (size_t)(m0 + tok) * NEXP + e);
        ls[tok][e] = __fadd_rn(lg, __fmul_rn(ev, sp));
    }
    __syncthreads();

    // ---- top-8 + softmax (one thread per token) ----
    if (tid < BM) {
        const int tok = tid;
        float vals[TOPK]; int idxs[TOPK];
        for (int k = 0; k < TOPK; k++) {
            float best = -3.402823466e38f; int bi = 0;
            for (int e = 0; e < NEXP; e++) {
                float v = ls[tok][e];
                if (v > best) { best = v; bi = e; }
            }
            vals[k] = best; idxs[k] = bi;
            ls[tok][bi] = -3.402823466e38f;
        }
        float mx = vals[0];
        float gsv[TOPK]; float s = 0.f;
        #pragma unroll
        for (int k = 0; k < TOPK; k++) { gsv[k] = expf(vals[k] - mx); s += gsv[k]; }
        float inv = 1.f / s;
        for (int e = 0; e < NEXP; e++) ls[tok][e] = 0.f;
        #pragma unroll
        for (int k = 0; k < TOPK; k++) ls[tok][idxs[k]] = gsv[k] * inv;
        #pragma unroll
        for (int k = 0; k < TOPK; k++) ls[tok][64 + k] = (float)idxs[k];
    }
    __syncthreads();

    // ---- cooperative coalesced stores ----
    #pragma unroll
    for (int i = 0; i < 16; i++) {
        int fid = tid + i * NTHREADS;
        int tok = fid >> 6;
        int e   = fid & 63;
        out_router[(size_t)(m0 + tok) * NEXP + e] = ls[tok][e];
    }
    #pragma unroll
    for (int i = 0; i < 2; i++) {
        int fid = tid + i * NTHREADS;
        int tok = fid >> 3;
        int k   = fid & 7;
        out_idx[(size_t)(m0 + tok) * TOPK + k] = ls[tok][64 + k];
    }
    if (tid < BM) {
        float z = ls[tid][128];
        out_skip[m0 + tid] = 1.f / (1.f + expf(-z));
    }
}

extern "C" void kernel_launch(void* const* d_in, const int* in_sizes, int n_in,
                              void* d_out, int out_size)
{
    const float* x     = (const float*)d_in[0];
    const float* eps   = (const float*)d_in[1];
    const float* wr    = (const float*)d_in[2];
    const float* br    = (const float*)d_in[3];
    const float* wn    = (const float*)d_in[4];
    const float* bn    = (const float*)d_in[5];
    const float* wskip = (const float*)d_in[6];
    const float* bskip = (const float*)d_in[7];

    float* out        = (float*)d_out;
    float* out_router = out;                                   // [32768, 64]
    float* out_idx    = out + (size_t)MTOK * NEXP;             // [32768, 8] as float
    float* out_skip   = out_idx + (size_t)MTOK * TOPK;         // [32768, 1]

    cudaFuncSetAttribute(router_kernel, cudaFuncAttributeMaxDynamicSharedMemorySize, SMEM_BYTES);
    router_kernel<<<MTOK / BM, NTHREADS, SMEM_BYTES>>>(x, eps, wr, br, wn, bn, wskip, bskip,
                                                       out_router, out_idx, out_skip);
}

// round 8
// speedup vs baseline: 1.2486x; 1.2486x over previous
#include <cuda_runtime.h>
#include <math.h>
#include <stdint.h>

// Problem constants
#define MTOK   32768
#define DDIM   2048
#define NEXP   64
#define TOPK   8
#define NCOLS  128            // router(64) || noise(64)

// Tiling: 128 threads, per-thread 8 tokens x 8 cols
#define BM      64
#define DK      32
#define NTHREADS 128          // tx = tid&15 (col group), ty = tid>>4 (token octet)
#define NKB     (DDIM / DK)   // 64 chunks

// smem: two buffers [xs | ws]; epilogue ls aliases buffer region.
#define XROW      68                          // xs row stride (floats): 16B-aligned rows
#define XS_BYTES  (DK * XROW * 4)             // 8704
#define WS_BYTES  (DK * NCOLS * 4)            // 16384
#define BUF_BYTES (XS_BYTES + WS_BYTES)       // 25088
#define SMEM_BYTES (2 * BUF_BYTES)            // 50176
#define LSTRIDE   133                         // 64*133*4 = 34048 <= SMEM_BYTES

typedef unsigned long long ull;

__device__ __forceinline__ void fma2(ull &acc, ull a, ull b) {
    asm("fma.rn.f32x2 %0, %1, %2, %0;" : "+l"(acc) : "l"(a), "l"(b));
}
__device__ __forceinline__ void add2(ull &acc, ull a) {
    asm("add.rn.f32x2 %0, %0, %1;" : "+l"(acc) : "l"(a));
}
__device__ __forceinline__ ull dup2(float w) {
    ull r; asm("mov.b64 %0, {%1, %1};" : "=l"(r) : "f"(w)); return r;
}
__device__ __forceinline__ float lo2(ull v) { return __uint_as_float((unsigned)v); }
__device__ __forceinline__ float hi2(ull v) { return __uint_as_float((unsigned)(v >> 32)); }

__device__ __forceinline__ void cp16(uint32_t dst_smem, const void* src) {
    asm volatile("cp.async.ca.shared.global [%0], [%1], 16;\n" :: "r"(dst_smem), "l"(src));
}
__device__ __forceinline__ void cp_commit() { asm volatile("cp.async.commit_group;\n"); }
__device__ __forceinline__ void cp_wait()   { asm volatile("cp.async.wait_group 0;\n" ::: "memory"); }

__global__ __launch_bounds__(NTHREADS) void router_kernel(
    const float* __restrict__ x,     const float* __restrict__ eps,
    const float* __restrict__ wr,    const float* __restrict__ br,
    const float* __restrict__ wn,    const float* __restrict__ bn,
    const float* __restrict__ wskip, const float* __restrict__ bskip,
    float* __restrict__ out_router, float* __restrict__ out_idx,
    float* __restrict__ out_skip)
{
    extern __shared__ __align__(16) unsigned char smem[];
    float (*ls)[LSTRIDE] = (float(*)[LSTRIDE])smem;   // epilogue only (aliases buffers)

    uint32_t sbase;
    asm("{ .reg .u64 t; cvta.to.shared.u64 t, %1; cvt.u32.u64 %0, t; }"
        : "=r"(sbase) : "l"(smem));

    const int tid  = threadIdx.x;
    const int tx   = tid & 15;       // cols {4tx+c, 4tx+64+c}, c=0..3
    const int ty   = tid >> 4;       // tokens 8ty .. 8ty+7
    const int ptok = tid >> 1;       // prefetch token 0..63
    const int pq   = (tid & 1) * 4;  // prefetch d-quad base (quads pq..pq+3)
    const int m0   = blockIdx.x * BM;

    // outer accumulators: acc[pr][c] = (tok 8ty+2pr, tok 8ty+2pr+1) x col(4tx + 64*(c>>2) + (c&3))
    ull acc[4][8];
    #pragma unroll
    for (int pr = 0; pr < 4; pr++)
        #pragma unroll
        for (int c = 0; c < 8; c++) acc[pr][c] = 0ull;
    float sk = 0.f;                  // skip partial: token ptok, d-quads pq..pq+3 of each chunk

    // ================= prologue: stage chunk 0 into buffer 0 =================
    float4 xr[4];
    {
        #pragma unroll
        for (int i = 0; i < 8; i++) {       // w panel: 1024 float4s
            int fid = tid + i * NTHREADS;
            int d   = fid >> 5;
            int col = (fid & 31) * 4;
            const float* src = (col < 64) ? (wr + (size_t)d * NEXP + col)
                                          : (wn + (size_t)d * NEXP + (col - 64));
            cp16(sbase + XS_BYTES + (uint32_t)(d * NCOLS + col) * 4, src);
        }
        cp_commit();
        #pragma unroll
        for (int i = 0; i < 4; i++) {
            int q = pq + i;
            xr[i] = *(const float4*)(x + (size_t)(m0 + ptok) * DDIM + q * 4);
            float4 w4 = *(const float4*)(wskip + q * 4);
            sk = fmaf(xr[i].x, w4.x, fmaf(xr[i].y, w4.y,
                 fmaf(xr[i].z, w4.z, fmaf(xr[i].w, w4.w, sk))));
        }
        float* xs0 = (float*)smem;
        #pragma unroll
        for (int i = 0; i < 4; i++) {
            int d0 = (pq + i) * 4;
            xs0[(d0 + 0) * XROW + ptok] = xr[i].x;
            xs0[(d0 + 1) * XROW + ptok] = xr[i].y;
            xs0[(d0 + 2) * XROW + ptok] = xr[i].z;
            xs0[(d0 + 3) * XROW + ptok] = xr[i].w;
        }
        cp_wait();
    }
    __syncthreads();

    // ================= main loop =================
    for (int kb = 0; kb < NKB; kb++) {
        const int cur = kb & 1;
        const float* xsb = (const float*)(smem + (size_t)cur * BUF_BYTES);
        const float* wsb = (const float*)(smem + (size_t)cur * BUF_BYTES + XS_BYTES);

        // ---- prefetch chunk kb+1 ----
        if (kb < NKB - 1) {
            const int k0 = (kb + 1) * DK;
            const uint32_t nxtoff = (uint32_t)(cur ^ 1) * BUF_BYTES;
            #pragma unroll
            for (int i = 0; i < 8; i++) {
                int fid = tid + i * NTHREADS;
                int d   = fid >> 5;
                int col = (fid & 31) * 4;
                const float* src = (col < 64) ? (wr + (size_t)(k0 + d) * NEXP + col)
                                              : (wn + (size_t)(k0 + d) * NEXP + (col - 64));
                cp16(sbase + nxtoff + XS_BYTES + (uint32_t)(d * NCOLS + col) * 4, src);
            }
            cp_commit();
            #pragma unroll
            for (int i = 0; i < 4; i++) {
                int q = pq + i;
                xr[i] = *(const float4*)(x + (size_t)(m0 + ptok) * DDIM + k0 + q * 4);
                float4 w4 = *(const float4*)(wskip + k0 + q * 4);
                sk = fmaf(xr[i].x, w4.x, fmaf(xr[i].y, w4.y,
                     fmaf(xr[i].z, w4.z, fmaf(xr[i].w, w4.w, sk))));
            }
        }

        // ---- FFMA2 mainloop: token-pair packing, w dup via mov ----
        ull inner[4][8];
        #pragma unroll
        for (int pr = 0; pr < 4; pr++)
            #pragma unroll
            for (int c = 0; c < 8; c++) inner[pr][c] = 0ull;

        #pragma unroll
        for (int d = 0; d < DK; d++) {
            ulonglong2 xv0 = *(const ulonglong2*)(xsb + d * XROW + 8 * ty);      // pairs (t0,t1),(t2,t3)
            ulonglong2 xv1 = *(const ulonglong2*)(xsb + d * XROW + 8 * ty + 4);  // pairs (t4,t5),(t6,t7)
            float4 wa = *(const float4*)(wsb + d * NCOLS + 4 * tx);
            float4 wb = *(const float4*)(wsb + d * NCOLS + 4 * tx + 64);
            ull xp[4] = {xv0.x, xv0.y, xv1.x, xv1.y};
            ull wd[8] = {dup2(wa.x), dup2(wa.y), dup2(wa.z), dup2(wa.w),
                         dup2(wb.x), dup2(wb.y), dup2(wb.z), dup2(wb.w)};
            #pragma unroll
            for (int pr = 0; pr < 4; pr++)
                #pragma unroll
                for (int c = 0; c < 8; c++)
                    fma2(inner[pr][c], xp[pr], wd[c]);
        }
        #pragma unroll
        for (int pr = 0; pr < 4; pr++)
            #pragma unroll
            for (int c = 0; c < 8; c++) add2(acc[pr][c], inner[pr][c]);

        // ---- store prefetched x into next buffer, drain cp.async ----
        if (kb < NKB - 1) {
            float* xsn = (float*)(smem + (size_t)(cur ^ 1) * BUF_BYTES);
            #pragma unroll
            for (int i = 0; i < 4; i++) {
                int d0 = (pq + i) * 4;
                xsn[(d0 + 0) * XROW + ptok] = xr[i].x;
                xsn[(d0 + 1) * XROW + ptok] = xr[i].y;
                xsn[(d0 + 2) * XROW + ptok] = xr[i].z;
                xsn[(d0 + 3) * XROW + ptok] = xr[i].w;
            }
            cp_wait();
        }
        __syncthreads();
    }

    // ---- stage logits (+bias) into ls (aliases buffers; all reads done) ----
    #pragma unroll
    for (int pr = 0; pr < 4; pr++) {
        int t0 = 8 * ty + 2 * pr;
        #pragma unroll
        for (int c = 0; c < 8; c++) {
            int col = 4 * tx + 64 * (c >> 2) + (c & 3);
            float b = (col < 64) ? __ldg(br + col) : __ldg(bn + col - 64);
            ls[t0][col]     = __fadd_rn(lo2(acc[pr][c]), b);
            ls[t0 + 1][col] = __fadd_rn(hi2(acc[pr][c]), b);
        }
    }
    // ---- skip-dot: combine the two half-token partials (lanes tid, tid^1) ----
    {
        float sko = __shfl_xor_sync(0xffffffffu, sk, 1);
        if ((tid & 1) == 0)
            ls[ptok][128] = __fadd_rn(sk + sko, __ldg(bskip));
    }
    __syncthreads();

    // ---- noisy logits: 4096 (tok,e) pairs over 128 threads ----
    #pragma unroll
    for (int i = 0; i < 32; i++) {
        int fid = tid + i * NTHREADS;
        int tok = fid >> 6;
        int e   = fid & 63;
        float  lg = ls[tok][e];
        float  no = ls[tok][64 + e];
        double nd = (double)no;
        float  sp = (float)(fmax(nd, 0.0) + log1p(exp(-fabs(nd))));
        float  ev = __ldg(eps + (size_t)(m0 + tok) * NEXP + e);
        ls[tok][e] = __fadd_rn(lg, __fmul_rn(ev, sp));
    }
    __syncthreads();

    // ---- top-8 + softmax (one thread per token) ----
    if (tid < BM) {
        const int tok = tid;
        float vals[TOPK]; int idxs[TOPK];
        for (int k = 0; k < TOPK; k++) {
            float best = -3.402823466e38f; int bi = 0;
            for (int e = 0; e < NEXP; e++) {
                float v = ls[tok][e];
                if (v > best) { best = v; bi = e; }
            }
            vals[k] = best; idxs[k] = bi;
            ls[tok][bi] = -3.402823466e38f;
        }
        float mx = vals[0];
        float gsv[TOPK]; float s = 0.f;
        #pragma unroll
        for (int k = 0; k < TOPK; k++) { gsv[k] = expf(vals[k] - mx); s += gsv[k]; }
        float inv = 1.f / s;
        for (int e = 0; e < NEXP; e++) ls[tok][e] = 0.f;
        #pragma unroll
        for (int k = 0; k < TOPK; k++) ls[tok][idxs[k]] = gsv[k] * inv;
        #pragma unroll
        for (int k = 0; k < TOPK; k++) ls[tok][64 + k] = (float)idxs[k];
    }
    __syncthreads();

    // ---- cooperative coalesced stores ----
    #pragma unroll
    for (int i = 0; i < 32; i++) {
        int fid = tid + i * NTHREADS;
        int tok = fid >> 6;
        int e   = fid & 63;
        out_router[(size_t)(m0 + tok) * NEXP + e] = ls[tok][e];
    }
    #pragma unroll
    for (int i = 0; i < 4; i++) {
        int fid = tid + i * NTHREADS;
        int tok = fid >> 3;
        int k   = fid & 7;
        out_idx[(size_t)(m0 + tok) * TOPK + k] = ls[tok][64 + k];
    }
    if (tid < BM) {
        float z = ls[tid][128];
        out_skip[m0 + tid] = 1.f / (1.f + expf(-z));
    }
}

extern "C" void kernel_launch(void* const* d_in, const int* in_sizes, int n_in,
                              void* d_out, int out_size)
{
    const float* x     = (const float*)d_in[0];
    const float* eps   = (const float*)d_in[1];
    const float* wr    = (const float*)d_in[2];
    const float* br    = (const float*)d_in[3];
    const float* wn    = (const float*)d_in[4];
    const float* bn    = (const float*)d_in[5];
    const float* wskip = (const float*)d_in[6];
    const float* bskip = (const float*)d_in[7];

    float* out        = (float*)d_out;
    float* out_router = out;                                   // [32768, 64]
    float* out_idx    = out + (size_t)MTOK * NEXP;             // [32768, 8] as float
    float* out_skip   = out_idx + (size_t)MTOK * TOPK;         // [32768, 1]

    cudaFuncSetAttribute(router_kernel, cudaFuncAttributeMaxDynamicSharedMemorySize, SMEM_BYTES);
    router_kernel<<<MTOK / BM, NTHREADS, SMEM_BYTES>>>(x, eps, wr, br, wn, bn, wskip, bskip,
                                                       out_router, out_idx, out_skip);
}